// round 17
// baseline (speedup 1.0000x reference)
#include <cuda_runtime.h>
#include <cuda_fp16.h>
#include <cstdint>

#define DEV_INLINE __device__ __forceinline__

// ---------------- problem sizes ----------------
static constexpr int kB = 16384;
static constexpr int kD = 1024;
static constexpr int kU = 128;

static constexpr int PAIR_BYTES = 128 * 128;     // 16384

// ---------------- spline kernel tiling ----------------
static constexpr int S_DC   = 32;
static constexpr int S_NCH  = kD / S_DC;         // 32
static constexpr int S_HALF = 3 * PAIR_BYTES;    // 49152 (A region or W region)
static constexpr int S_BUF  = 2 * S_HALF;        // 98304
static constexpr int S_SMEM = 2 * S_BUF;         // 196608
static constexpr int S_W_U4 = 3 * 16384 / 16;    // 3072 uint4/chunk (48KB)

// ---------------- base kernel tiling ----------------
static constexpr int B_DC  = 64;
static constexpr int B_NCH = kD / B_DC;          // 16
static constexpr int B_AREG = PAIR_BYTES;        // 16384
static constexpr int B_BUF  = B_AREG + 16384;    // A 16K + W 16K = 32768
static constexpr int B_SMEM = 2 * B_BUF;         // 65536
static constexpr int B_W_U4 = 16384 / 16;        // 1024

static constexpr int NTHREADS = 384;   // 4 producer warps (0-3) + 8 consumer warps (4-11)

// packed weights
__device__ __half g_WbPack[16 * 8192];     // base:   [c16][n128][k64] SW128
__device__ __half g_WsPack[96 * 8192];     // spline: [c32][p3][n128][2 streams] SW128

// ---------------- PTX helpers ----------------
DEV_INLINE uint32_t smem_u32(const void* p) {
    uint32_t a;
    asm("{ .reg .u64 t; cvta.to.shared.u64 t, %1; cvt.u32.u64 %0, t; }" : "=r"(a) : "l"(p));
    return a;
}

#define LDSM_X4(r, addr)                                                        \
    asm volatile("ldmatrix.sync.aligned.m8n8.x4.shared.b16 {%0,%1,%2,%3}, [%4];"\
                 : "=r"((r)[0]), "=r"((r)[1]), "=r"((r)[2]), "=r"((r)[3])       \
                 : "r"(addr))

DEV_INLINE void mma16816(float* d, const uint32_t* a, uint32_t b0, uint32_t b1) {
    asm volatile(
        "mma.sync.aligned.m16n8k16.row.col.f32.f16.f16.f32 "
        "{%0,%1,%2,%3}, {%4,%5,%6,%7}, {%8,%9}, {%0,%1,%2,%3};"
        : "+f"(d[0]), "+f"(d[1]), "+f"(d[2]), "+f"(d[3])
        : "r"(a[0]), "r"(a[1]), "r"(a[2]), "r"(a[3]), "r"(b0), "r"(b1));
}

DEV_INLINE void cp_async16(uint32_t smem_dst, const void* gsrc) {
    asm volatile("cp.async.cg.shared.global [%0], [%1], 16;"
                 :: "r"(smem_dst), "l"(gsrc) : "memory");
}
DEV_INLINE void cp_async_commit() { asm volatile("cp.async.commit_group;" ::: "memory"); }
DEV_INLINE void cp_async_wait_all() { asm volatile("cp.async.wait_group 0;" ::: "memory"); }

// ---------------- weight prep: vectorized (one uint4 store per thread) ----------------
__global__ void kan_prep_weights(const float* __restrict__ bw,
                                 const float* __restrict__ sw) {
    int u = blockIdx.x * blockDim.x + threadIdx.x;
    if (u < 16384) {
        // base pack: [c16][n128][k64 halves]
        int g16 = u & 7;
        int n   = (u >> 3) & 127;
        int c   = u >> 10;
        int k0  = g16 * 8;
        __half h[8];
        #pragma unroll
        for (int j = 0; j < 8; ++j)
            h[j] = __float2half(bw[(c * 64 + k0 + j) * kU + n]);
        unsigned off = (unsigned)(n * 128 + k0 * 2);
        unsigned swz = off ^ ((off >> 3) & 0x70);
        *reinterpret_cast<uint4*>(reinterpret_cast<char*>(g_WbPack) +
                                  (size_t)c * 16384 + swz) =
            *reinterpret_cast<const uint4*>(h);
    } else if (u < 16384 + 98304) {
        // spline pack: [c32][p3][n128][2 streams x 32 k halves]
        int v   = u - 16384;
        int g16 = v & 7;
        int n   = (v >> 3) & 127;
        int t3  = v >> 10;            // c*3 + p
        int slo = g16 >> 2;
        int k0  = (g16 & 3) * 8;
        int p   = t3 % 3;
        int c   = t3 / 3;
        int s   = p * 2 + slo;        // stream 0..5; s<5 real, s==5 zero pad
        __half h[8];
        #pragma unroll
        for (int j = 0; j < 8; ++j) {
            int i = c * S_DC + k0 + j;
            float val = (s < 5) ? sw[(size_t)(i * kU + n) * 8 + s] : 0.f;
            h[j] = __float2half(val);
        }
        unsigned off = (unsigned)(n * 128 + slo * 64 + k0 * 2);
        unsigned swz = off ^ ((off >> 3) & 0x70);
        *reinterpret_cast<uint4*>(reinterpret_cast<char*>(g_WsPack) +
                                  (size_t)t3 * 16384 + swz) =
            *reinterpret_cast<const uint4*>(h);
    }
}

// ---- 64x32 consumer load/mma macros ----
#define CLD(OFF, KB, FA, FB) do {                                               \
    LDSM_X4(&(FB)[0], bBase + (OFF) + bOff + (((KB) + 0u)  ^ bXor));            \
    LDSM_X4(&(FB)[4], bBase + (OFF) + bOff + (((KB) + 16u) ^ bXor));            \
    {                                                                           \
        const uint32_t kbA_ = (KB) + kbAhi;                                     \
        _Pragma("unroll")                                                       \
        for (int mb_ = 0; mb_ < 4; ++mb_)                                       \
            LDSM_X4(&(FA)[mb_ * 4],                                             \
                    aBase + (OFF) + aOff[mb_] + (kbA_ ^ aXor[mb_]));            \
    }                                                                           \
} while (0)

#define CMMA(ACC, FA, FB) do {                                                  \
    _Pragma("unroll")                                                           \
    for (int mb_ = 0; mb_ < 4; ++mb_)                                           \
        _Pragma("unroll")                                                       \
        for (int nb_ = 0; nb_ < 4; ++nb_)                                       \
            mma16816((ACC)[mb_][nb_], &(FA)[mb_ * 4], (FB)[nb_], (FB)[4 + nb_]);\
} while (0)

// =======================================================================
// BASE kernel: out = SiLU(x @ Wb). 4 producers + 8 consumers, pipelined.
// =======================================================================
__global__ void __launch_bounds__(NTHREADS, 1)
kan_base_kernel(const float* __restrict__ x, float* __restrict__ out) {
    extern __shared__ char smem[];
    const uint32_t smem_base = smem_u32(smem);
    const int tid  = threadIdx.x;
    const int wid  = tid >> 5;
    const int lane = tid & 31;
    const int row_base = blockIdx.x * 128;

    if (wid < 4) {
        // producers: 128 threads, 1 row x 64 cols each
        const int pr = tid;
        const float* xp = x + (size_t)(row_base + pr) * kD;
        const unsigned rowOff = (unsigned)(pr * 128);
        const unsigned rXor   = (unsigned)((pr & 7) << 4);

        float4 xq[16];
        auto loadX = [&](int c) {
            const float* p = xp + c * B_DC;
            #pragma unroll
            for (int j = 0; j < 16; ++j)
                xq[j] = *reinterpret_cast<const float4*>(p + j * 4);
        };
        auto produce = [&](uint32_t bufOff) {
            #pragma unroll
            for (int g = 0; g < 8; ++g) {
                union { __half2 h2[4]; uint4 u4; } st;
                st.h2[0] = __floats2half2_rn(xq[2*g].x,   xq[2*g].y);
                st.h2[1] = __floats2half2_rn(xq[2*g].z,   xq[2*g].w);
                st.h2[2] = __floats2half2_rn(xq[2*g+1].x, xq[2*g+1].y);
                st.h2[3] = __floats2half2_rn(xq[2*g+1].z, xq[2*g+1].w);
                unsigned off = rowOff + (unsigned)(g * 16);
                unsigned swz = off ^ rXor;
                *reinterpret_cast<uint4*>(smem + bufOff + swz) = st.u4;
            }
        };
        auto copyW = [&](int c, uint32_t bufOff) {
            const char* src = reinterpret_cast<const char*>(g_WbPack) + (size_t)c * 16384;
            #pragma unroll
            for (int j = 0; j < B_W_U4 / 128; ++j) {
                int i = pr + j * 128;
                cp_async16(smem_base + bufOff + B_AREG + i * 16, src + i * 16);
            }
            cp_async_commit();
        };

        copyW(0, 0);
        loadX(0);
        produce(0);
        cp_async_wait_all();
        __syncthreads();

        for (int c = 0; c < B_NCH; ++c) {
            if (c + 1 < B_NCH) {
                uint32_t bo = (uint32_t)(((c + 1) & 1) * B_BUF);
                copyW(c + 1, bo);
                loadX(c + 1);
                produce(bo);
                cp_async_wait_all();
            }
            __syncthreads();
        }
    } else {
        // consumers: 8 warps, 64x32 tiles, frag double-buffered
        const int w  = wid - 4;
        const int mi = w & 1;
        const int ni = w >> 1;

        float acc[4][4][4];
        #pragma unroll
        for (int a = 0; a < 4; ++a)
            #pragma unroll
            for (int b = 0; b < 4; ++b)
                #pragma unroll
                for (int j = 0; j < 4; ++j) acc[a][b][j] = 0.f;

        const int aRowLocal  = (lane & 7) + ((lane >> 3) & 1) * 8;
        const uint32_t kbAhi = ((lane >> 4) & 1) * 16;
        uint32_t aOff[4], aXor[4];
        #pragma unroll
        for (int mb = 0; mb < 4; ++mb) {
            int r = mi * 64 + mb * 16 + aRowLocal;
            aOff[mb] = (uint32_t)(r * 128);
            aXor[mb] = (uint32_t)((r & 7) << 4);
        }
        const int rB = ni * 32 + lane;
        const uint32_t bOff = (uint32_t)(B_AREG + rB * 128);
        const uint32_t bXor = (uint32_t)((rB & 7) << 4);

        __syncthreads();

        uint32_t fa0[16], fa1[16], fb0[8], fb1[8];
        for (int c = 0; c < B_NCH; ++c) {
            const uint32_t bo = (uint32_t)((c & 1) * B_BUF);
            const uint32_t aBase = smem_base + bo;
            const uint32_t bBase = smem_base + bo;
            CLD(0u, 0u,  fa0, fb0);
            CLD(0u, 32u, fa1, fb1);  CMMA(acc, fa0, fb0);
            CLD(0u, 64u, fa0, fb0);  CMMA(acc, fa1, fb1);
            CLD(0u, 96u, fa1, fb1);  CMMA(acc, fa0, fb0);
                                     CMMA(acc, fa1, fb1);
            __syncthreads();
        }

        // epilogue: SiLU, store
        const int colBase = ni * 32 + (lane & 3) * 2;
        #pragma unroll
        for (int mb = 0; mb < 4; ++mb) {
            int row0 = row_base + mi * 64 + mb * 16 + (lane >> 2);
            #pragma unroll
            for (int nb = 0; nb < 4; ++nb) {
                int col = colBase + nb * 8;
                float z0 = acc[mb][nb][0], z1 = acc[mb][nb][1];
                float z2 = acc[mb][nb][2], z3 = acc[mb][nb][3];
                float2 v0, v1;
                v0.x = __fdividef(z0, 1.f + __expf(-z0));
                v0.y = __fdividef(z1, 1.f + __expf(-z1));
                v1.x = __fdividef(z2, 1.f + __expf(-z2));
                v1.y = __fdividef(z3, 1.f + __expf(-z3));
                *reinterpret_cast<float2*>(out + (size_t)row0 * kU + col)       = v0;
                *reinterpret_cast<float2*>(out + (size_t)(row0 + 8) * kU + col) = v1;
            }
        }
    }
}

// =======================================================================
// SPLINE kernel: out += rbf-einsum. 4 producers + 8 consumers, pipelined.
// =======================================================================
__global__ void __launch_bounds__(NTHREADS, 1)
kan_spline_kernel(const float* __restrict__ x, float* __restrict__ out) {
    extern __shared__ char smem[];
    const uint32_t smem_base = smem_u32(smem);
    const int tid  = threadIdx.x;
    const int wid  = tid >> 5;
    const int lane = tid & 31;
    const int row_base = blockIdx.x * 128;

    const float E375p = 42.52108200006278f;    // e^{3.75}
    const float E125p = 3.4903429574597902f;   // e^{1.25}
    const float E125m = 0.2865047968601901f;   // e^{-1.25}
    const float E375m = 0.023517745856009107f; // e^{-3.75}

    if (wid < 4) {
        // producers: 128 threads, 1 row x 32 cols each, 5 rbf streams
        const int pr = tid;
        const float* xp = x + (size_t)(row_base + pr) * kD;
        const uint32_t aSw = (uint32_t)((pr & 7) << 4);

        float4 xq[8];
        auto loadX = [&](int c) {
            const float* p = xp + c * S_DC;
            #pragma unroll
            for (int j = 0; j < 8; ++j)
                xq[j] = *reinterpret_cast<const float4*>(p + j * 4);
        };
        auto produce = [&](uint32_t bufOff) {
            #pragma unroll
            for (int g = 0; g < 4; ++g) {
                float xs[8];
                xs[0]=xq[2*g].x;   xs[1]=xq[2*g].y;   xs[2]=xq[2*g].z;   xs[3]=xq[2*g].w;
                xs[4]=xq[2*g+1].x; xs[5]=xq[2*g+1].y; xs[6]=xq[2*g+1].z; xs[7]=xq[2*g+1].w;
                union { __half2 h2[4]; uint4 u4; } st[5];
                #pragma unroll
                for (int e = 0; e < 8; e += 2) {
                    float a0 = xs[e] + 1.f, a1 = xs[e+1] + 1.f;
                    float y0a = __expf(-5.f * a0 * a0);
                    float y0b = __expf(-5.f * a1 * a1);
                    float ta  = __expf(5.f * xs[e]);
                    float tb  = __expf(5.f * xs[e+1]);
                    float y1a = y0a * ta * E375p, y1b = y0b * tb * E375p;
                    float y2a = y1a * ta * E125p, y2b = y1b * tb * E125p;
                    float y3a = y2a * ta * E125m, y3b = y2b * tb * E125m;
                    float y4a = y3a * ta * E375m, y4b = y3b * tb * E375m;
                    int j = e >> 1;
                    st[0].h2[j] = __floats2half2_rn(y0a, y0b);
                    st[1].h2[j] = __floats2half2_rn(y1a, y1b);
                    st[2].h2[j] = __floats2half2_rn(y2a, y2b);
                    st[3].h2[j] = __floats2half2_rn(y3a, y3b);
                    st[4].h2[j] = __floats2half2_rn(y4a, y4b);
                }
                #pragma unroll
                for (int s = 0; s < 5; ++s) {
                    int p = s >> 1, slo = s & 1;
                    unsigned off = (unsigned)(pr * 128 + slo * 64 + g * 16);
                    unsigned swz = off ^ aSw;
                    *reinterpret_cast<uint4*>(smem + bufOff + p * PAIR_BYTES + swz)
                        = st[s].u4;
                }
            }
        };
        auto copyW = [&](int c, uint32_t bufOff) {
            const char* src = reinterpret_cast<const char*>(g_WsPack) +
                              (size_t)c * (3 * 16384);
            #pragma unroll
            for (int j = 0; j < S_W_U4 / 128; ++j) {  // 24 per thread
                int i = pr + j * 128;
                cp_async16(smem_base + bufOff + S_HALF + i * 16, src + i * 16);
            }
            cp_async_commit();
        };

        loadX(0);
        copyW(0, 0);
        produce(0);
        if (S_NCH > 1) loadX(1);
        cp_async_wait_all();
        __syncthreads();

        for (int c = 0; c < S_NCH; ++c) {
            if (c + 1 < S_NCH) {
                uint32_t bo = (uint32_t)(((c + 1) & 1) * S_BUF);
                copyW(c + 1, bo);
                produce(bo);                       // x(c+1) already in regs
                if (c + 2 < S_NCH) loadX(c + 2);
                cp_async_wait_all();
            }
            __syncthreads();
        }
    } else {
        // consumers: 8 warps, 64x32 tiles, 10 steps/chunk, frag double-buffered
        const int w  = wid - 4;
        const int mi = w & 1;
        const int ni = w >> 1;

        float acc[4][4][4];
        #pragma unroll
        for (int a = 0; a < 4; ++a)
            #pragma unroll
            for (int b = 0; b < 4; ++b)
                #pragma unroll
                for (int j = 0; j < 4; ++j) acc[a][b][j] = 0.f;

        const int aRowLocal  = (lane & 7) + ((lane >> 3) & 1) * 8;
        const uint32_t kbAhi = ((lane >> 4) & 1) * 16;
        uint32_t aOff[4], aXor[4];
        #pragma unroll
        for (int mb = 0; mb < 4; ++mb) {
            int r = mi * 64 + mb * 16 + aRowLocal;
            aOff[mb] = (uint32_t)(r * 128);
            aXor[mb] = (uint32_t)((r & 7) << 4);
        }
        const int rB = ni * 32 + lane;
        const uint32_t bOff = (uint32_t)(S_HALF + rB * 128);
        const uint32_t bXor = (uint32_t)((rB & 7) << 4);

        __syncthreads();

        // step T (0..9): stream s = T>>1 (pair p = s>>1, slo = s&1), kk = T&1
#define S_LD(T, FA, FB)                                                         \
        CLD((uint32_t)((((T) >> 1) >> 1) * PAIR_BYTES),                         \
            (uint32_t)(((((T) >> 1) & 1) * 64) + (((T) & 1) * 32)), FA, FB)

        uint32_t fa0[16], fa1[16], fb0[8], fb1[8];
        for (int c = 0; c < S_NCH; ++c) {
            const uint32_t bo = (uint32_t)((c & 1) * S_BUF);
            const uint32_t aBase = smem_base + bo;
            const uint32_t bBase = smem_base + bo;
            S_LD(0, fa0, fb0);
            S_LD(1, fa1, fb1);  CMMA(acc, fa0, fb0);
            S_LD(2, fa0, fb0);  CMMA(acc, fa1, fb1);
            S_LD(3, fa1, fb1);  CMMA(acc, fa0, fb0);
            S_LD(4, fa0, fb0);  CMMA(acc, fa1, fb1);
            S_LD(5, fa1, fb1);  CMMA(acc, fa0, fb0);
            S_LD(6, fa0, fb0);  CMMA(acc, fa1, fb1);
            S_LD(7, fa1, fb1);  CMMA(acc, fa0, fb0);
            S_LD(8, fa0, fb0);  CMMA(acc, fa1, fb1);
            S_LD(9, fa1, fb1);  CMMA(acc, fa0, fb0);
                                CMMA(acc, fa1, fb1);
            __syncthreads();
        }
#undef S_LD

        // epilogue: out += spline (out holds SiLU(base))
        const int colBase = ni * 32 + (lane & 3) * 2;
        #pragma unroll
        for (int mb = 0; mb < 4; ++mb) {
            int row0 = row_base + mi * 64 + mb * 16 + (lane >> 2);
            #pragma unroll
            for (int nb = 0; nb < 4; ++nb) {
                int col = colBase + nb * 8;
                float2* p0 = reinterpret_cast<float2*>(out + (size_t)row0 * kU + col);
                float2* p1 = reinterpret_cast<float2*>(out + (size_t)(row0 + 8) * kU + col);
                float2 v0 = *p0, v1 = *p1;
                v0.x += acc[mb][nb][0]; v0.y += acc[mb][nb][1];
                v1.x += acc[mb][nb][2]; v1.y += acc[mb][nb][3];
                *p0 = v0; *p1 = v1;
            }
        }
    }
}

// ---------------- launch ----------------
extern "C" void kernel_launch(void* const* d_in, const int* in_sizes, int n_in,
                              void* d_out, int out_size) {
    (void)in_sizes; (void)n_in; (void)out_size;
    const float* x  = (const float*)d_in[0];
    const float* bw = (const float*)d_in[1];
    const float* sw = (const float*)d_in[2];
    float* out = (float*)d_out;

    cudaFuncSetAttribute(kan_base_kernel,
                         cudaFuncAttributeMaxDynamicSharedMemorySize, B_SMEM);
    cudaFuncSetAttribute(kan_spline_kernel,
                         cudaFuncAttributeMaxDynamicSharedMemorySize, S_SMEM);

    kan_prep_weights<<<(16384 + 98304 + 255) / 256, 256>>>(bw, sw);
    kan_base_kernel<<<kB / 128, NTHREADS, B_SMEM>>>(x, out);
    kan_spline_kernel<<<kB / 128, NTHREADS, S_SMEM>>>(x, out);
}